// round 4
// baseline (speedup 1.0000x reference)
#include <cuda_runtime.h>

#define NG 1024
#define NN 40
#define M_EDGES 780
#define NODES (NG*NN)          /* 40960 */
#define H_ELEMS (NODES*64)     /* 2621440 */
#define X_PER_G (160*160)      /* 25600 */
#define X_ELEMS ((size_t)NG*X_PER_G)

// scratch: u = hg @ We0 per node (10.5 MB, fits in L2)
__device__ float g_u[NODES * 64];
// fallback scratch if the harness's d_out does not cover h and/or X
__device__ float g_h[H_ELEMS];
__device__ float g_x[NG * X_PER_G];

__constant__ int c_smat[16] = {0,1,2,3, 1,4,5,6, 2,5,7,8, 3,6,8,9};

__device__ __forceinline__ float lrelu(float v){ return v > 0.f ? v : 0.1f*v; }

// packed fp32x2 FMA (sm_10x): 2 MACs per instruction
__device__ __forceinline__ unsigned long long ffma2(unsigned long long a, unsigned long long b, unsigned long long c){
    unsigned long long d;
    asm("fma.rn.f32x2 %0, %1, %2, %3;" : "=l"(d) : "l"(a), "l"(b), "l"(c));
    return d;
}
__device__ __forceinline__ unsigned long long splat2(float x){
    unsigned long long r;
    asm("mov.b64 %0, {%1, %1};" : "=l"(r) : "f"(x));
    return r;
}
__device__ __forceinline__ float f2lo(unsigned long long a){ return __uint_as_float((unsigned)(a & 0xffffffffULL)); }
__device__ __forceinline__ float f2hi(unsigned long long a){ return __uint_as_float((unsigned)(a >> 32)); }

// ---------------------------------------------------------------------------
// K1: GCN — complete graph => gcn(h)[j] = (colsum(t) - t[j])/39 + b, t = h@W
// ---------------------------------------------------------------------------
__global__ __launch_bounds__(128) void gcn_kernel(
    const float* __restrict__ x,
    const float* __restrict__ Wg0, const float* __restrict__ bg0,
    const float* __restrict__ Wg1, const float* __restrict__ bg1,
    const float* __restrict__ Wg2, const float* __restrict__ bg2,
    float* __restrict__ hout)
{
    __shared__ float sh[NN*64];
    __shared__ float st[NN*64];
    __shared__ float sw[32*64];
    __shared__ float ssum[64];
    const int g = blockIdx.x, tid = threadIdx.x;

    for (int idx = tid; idx < NN*6; idx += 128){
        int n = idx/6, c = idx - n*6;
        sh[n*64+c] = x[(g*NN+n)*16 + c];
    }
    __syncthreads();

    auto layer = [&](int ind, int outd, const float* W, const float* b, bool act){
        for (int idx = tid; idx < ind*outd; idx += 128) sw[idx] = W[idx];
        __syncthreads();
        for (int idx = tid; idx < NN*outd; idx += 128){
            int n = idx/outd, o = idx - n*outd;
            float a = 0.f;
            for (int k = 0; k < ind; k++) a += sh[n*64+k]*sw[k*outd+o];
            st[n*64+o] = a;
        }
        __syncthreads();
        for (int o = tid; o < outd; o += 128){
            float s = 0.f;
            for (int n = 0; n < NN; n++) s += st[n*64+o];
            ssum[o] = s;
        }
        __syncthreads();
        const float inv = 1.f/39.f;
        for (int idx = tid; idx < NN*outd; idx += 128){
            int n = idx/outd, o = idx - n*outd;
            float v = (ssum[o] - st[n*64+o])*inv + b[o];
            if (act) v = lrelu(v);
            sh[n*64+o] = v;
        }
        __syncthreads();
    };
    layer(6, 32, Wg0, bg0, true);
    layer(32, 32, Wg1, bg1, true);
    layer(32, 64, Wg2, bg2, false);

    float* hrow = hout + (size_t)g*NN*64;
    for (int idx = tid; idx < NN*64; idx += 128) hrow[idx] = sh[idx];
}

// ---------------------------------------------------------------------------
// 64x64x64 GEMM tile, 128 threads, thread tile = 4 rows x 8 outs, FFMA2 packed
// Zin: [k][row] stride 64 (shared). Wsp: splatted weights [k][o]{w,w} stride 128.
// Zout: [o][row] stride 64.
// ---------------------------------------------------------------------------
template<bool ACT, bool HASB>
__device__ __forceinline__ void gemm64(const float* Zin, float* Zout,
                                       const float* Wsp, const float* bias,
                                       int eg, int og)
{
    unsigned long long acc[16];
#pragma unroll
    for (int i = 0; i < 16; i++) acc[i] = 0ULL;

#pragma unroll 4
    for (int k = 0; k < 64; k++){
        ulonglong2 z = *reinterpret_cast<const ulonglong2*>(Zin + k*64 + eg*4);
        const ulonglong2* wp = reinterpret_cast<const ulonglong2*>(Wsp + k*128 + og*16);
        ulonglong2 w0 = wp[0], w1 = wp[1], w2 = wp[2], w3 = wp[3];
        acc[0] = ffma2(z.x, w0.x, acc[0]);  acc[1]  = ffma2(z.y, w0.x, acc[1]);
        acc[2] = ffma2(z.x, w0.y, acc[2]);  acc[3]  = ffma2(z.y, w0.y, acc[3]);
        acc[4] = ffma2(z.x, w1.x, acc[4]);  acc[5]  = ffma2(z.y, w1.x, acc[5]);
        acc[6] = ffma2(z.x, w1.y, acc[6]);  acc[7]  = ffma2(z.y, w1.y, acc[7]);
        acc[8] = ffma2(z.x, w2.x, acc[8]);  acc[9]  = ffma2(z.y, w2.x, acc[9]);
        acc[10]= ffma2(z.x, w2.y, acc[10]); acc[11] = ffma2(z.y, w2.y, acc[11]);
        acc[12]= ffma2(z.x, w3.x, acc[12]); acc[13] = ffma2(z.y, w3.x, acc[13]);
        acc[14]= ffma2(z.x, w3.y, acc[14]); acc[15] = ffma2(z.y, w3.y, acc[15]);
    }
#pragma unroll
    for (int o = 0; o < 8; o++){
        float b = HASB ? bias[og*8+o] : 0.f;
#pragma unroll
        for (int p = 0; p < 2; p++){
            unsigned long long A = acc[o*2+p];
            float lo = f2lo(A) + b;
            float hi = f2hi(A) + b;
            if (ACT){ lo = lrelu(lo); hi = lrelu(hi); }
            *reinterpret_cast<float2*>(Zout + (og*8+o)*64 + eg*4 + p*2) = make_float2(lo, hi);
        }
    }
}

// Final 64->10 layer: threads split (row e, k-half kh). Partial sums into `part`.
__device__ __forceinline__ void layer10(const float* Zin, const float* wsh,
                                        float* part, int e, int kh)
{
    unsigned long long acc[5];
#pragma unroll
    for (int p = 0; p < 5; p++) acc[p] = 0ULL;
    const int k0 = kh*32;
#pragma unroll 4
    for (int kk = 0; kk < 32; kk++){
        int k = k0 + kk;
        unsigned long long z2 = splat2(Zin[k*64+e]);
        const float* wr = wsh + k*10;
#pragma unroll
        for (int p = 0; p < 5; p++){
            unsigned long long w = *reinterpret_cast<const unsigned long long*>(wr + p*2);
            acc[p] = ffma2(z2, w, acc[p]);
        }
    }
    float* pr = part + kh*640 + e*10;
#pragma unroll
    for (int p = 0; p < 5; p++){ pr[p*2] = f2lo(acc[p]); pr[p*2+1] = f2hi(acc[p]); }
}

__device__ __forceinline__ void splatW(const float* __restrict__ W, float* Wsp, int tid){
    for (int idx = tid; idx < 4096; idx += 128){
        float w = W[idx];
        int k = idx >> 6, o = idx & 63;
        *reinterpret_cast<float2*>(Wsp + k*128 + o*2) = make_float2(w, w);
    }
}

// ---------------------------------------------------------------------------
// K2: per-node — u = hg@We0 (store), vp = MLP(hg) -> diagonal 4x4 blocks of X
// 64 nodes per block, 128 threads
// ---------------------------------------------------------------------------
#define K2_SMEM_FLOATS 18384
__global__ __launch_bounds__(128) void node_kernel(
    const float* __restrict__ hg,
    const float* __restrict__ Wn0, const float* __restrict__ bn0,
    const float* __restrict__ Wn1, const float* __restrict__ bn1,
    const float* __restrict__ Wn2, const float* __restrict__ bn2,
    const float* __restrict__ We0,
    float* __restrict__ Xout)
{
    extern __shared__ float sm[];
    float* Z0   = sm;             // 4096
    float* Za   = sm + 4096;      // 4096
    float* Wsp  = sm + 8192;      // 8192
    float* wsh  = sm + 16384;     // 640
    float* part = sm + 17024;     // 1280
    float* bsh  = sm + 18304;     // 64
    float* b2   = sm + 18368;     // 16

    const int tid = threadIdx.x;
    const int e  = tid & 63, kh = tid >> 6;
    const int eg = tid & 15, og = tid >> 4;
    const int r0 = blockIdx.x * 64;

    // transpose-load: Z0[k][e] = hg[r0+e][k]
    {
        const float4* row = reinterpret_cast<const float4*>(hg + (size_t)(r0+e)*64);
#pragma unroll
        for (int q = 0; q < 8; q++){
            float4 v = row[kh*8+q];
            int k = kh*32 + q*4;
            Z0[(k+0)*64+e]=v.x; Z0[(k+1)*64+e]=v.y; Z0[(k+2)*64+e]=v.z; Z0[(k+3)*64+e]=v.w;
        }
    }
    splatW(We0, Wsp, tid);
    __syncthreads();
    gemm64<false,false>(Z0, Za, Wsp, nullptr, eg, og);   // u (no bias/act)
    __syncthreads();
    {
        float4* urow = reinterpret_cast<float4*>(g_u + (size_t)(r0+e)*64);
#pragma unroll
        for (int q = 0; q < 8; q++){
            int k = kh*32 + q*4;
            urow[kh*8+q] = make_float4(Za[k*64+e], Za[(k+1)*64+e], Za[(k+2)*64+e], Za[(k+3)*64+e]);
        }
    }
    __syncthreads();
    splatW(Wn0, Wsp, tid);
    for (int i2 = tid; i2 < 64; i2 += 128) bsh[i2] = bn0[i2];
    __syncthreads();
    gemm64<true,true>(Z0, Za, Wsp, bsh, eg, og);
    __syncthreads();
    splatW(Wn1, Wsp, tid);
    for (int i2 = tid; i2 < 64; i2 += 128) bsh[i2] = bn1[i2];
    __syncthreads();
    gemm64<true,true>(Za, Z0, Wsp, bsh, eg, og);
    __syncthreads();
    for (int i2 = tid; i2 < 640; i2 += 128) wsh[i2] = Wn2[i2];
    if (tid < 10) b2[tid] = bn2[tid];
    __syncthreads();
    layer10(Z0, wsh, part, e, kh);
    __syncthreads();

    // diagonal 4x4 blocks: X[g, i*4+a, i*4 .. i*4+3]
#pragma unroll
    for (int p = 0; p < 2; p++){
        int idx = tid + p*128;             // 0..255
        int n = idx >> 2, a = idx & 3;
        int r = r0 + n, gg = r/40, i = r - gg*40;
        const float* p0 = part + n*10;
        const float* p1 = part + 640 + n*10;
        int s0=c_smat[a*4], s1=c_smat[a*4+1], s2=c_smat[a*4+2], s3=c_smat[a*4+3];
        float4 v = make_float4(p0[s0]+p1[s0]+b2[s0], p0[s1]+p1[s1]+b2[s1],
                               p0[s2]+p1[s2]+b2[s2], p0[s3]+p1[s3]+b2[s3]);
        *reinterpret_cast<float4*>(Xout + (size_t)gg*X_PER_G + (i*4+a)*160 + i*4) = v;
    }
}

// ---------------------------------------------------------------------------
// K3: per-edge — z1 = lrelu(u_i + u_j + be0); z2 = lrelu(z1@We1+be1);
//     ep = z2@We2+be2; write symmetric 4x4 block to X at (i,j) and (j,i).
// block = 64 edges of one group (grid: 13 tiles x 1024 groups), 128 threads
// ---------------------------------------------------------------------------
#define K3_SMEM_FLOATS 21184
__global__ __launch_bounds__(128) void edge_kernel(
    const int* __restrict__ ud,   /* int32: JAX x64 is disabled */
    const float* __restrict__ be0,
    const float* __restrict__ We1, const float* __restrict__ be1,
    const float* __restrict__ We2, const float* __restrict__ be2,
    float* __restrict__ Xout)
{
    extern __shared__ float sm[];
    float* ug   = sm;              // 40*65 = 2600 (pad 2608)
    float* Z0   = sm + 2608;       // 4096
    float* Za   = sm + 6704;       // 4096
    float* Wsp  = sm + 10800;      // 8192
    float* wsh  = sm + 18992;      // 640
    float* part = sm + 19632;      // 1280
    float* b0   = sm + 20912;      // 64
    float* b1   = sm + 20976;      // 64
    float* b2   = sm + 21040;      // 16
    int*   si   = (int*)(sm + 21056); // 64
    int*   sj   = (int*)(sm + 21120); // 64

    const int tid = threadIdx.x;
    const int e  = tid & 63, kh = tid >> 6;
    const int eg = tid & 15, og = tid >> 4;
    const int g = blockIdx.y, tile = blockIdx.x;
    const int m0 = tile*64;
    const int ecnt = min(64, M_EDGES - m0);

    {   // group's u rows into shared, stride 65 (conflict-free later reads)
        const float* usrc = g_u + (size_t)g*NN*64;
        for (int idx = tid; idx < NN*64; idx += 128){
            int n = idx >> 6, k = idx & 63;
            ug[n*65+k] = usrc[idx];
        }
    }
    splatW(We1, Wsp, tid);
    for (int i2 = tid; i2 < 64; i2 += 128){ b0[i2] = be0[i2]; b1[i2] = be1[i2]; }
    for (int i2 = tid; i2 < 640; i2 += 128) wsh[i2] = We2[i2];
    if (tid < 10) b2[tid] = be2[tid];
    if (tid < 64){
        int ii = 0, jj = 0;
        if (tid < ecnt){ ii = ud[2*(m0+tid)]; jj = ud[2*(m0+tid)+1]; }
        si[tid] = ii; sj[tid] = jj;
    }
    __syncthreads();

    {   // z1
        const bool valid = e < ecnt;
        const int i = si[e], j = sj[e];
        const float* ui = ug + i*65;
        const float* uj = ug + j*65;
        for (int k = kh*32; k < kh*32+32; k++){
            float v = 0.f;
            if (valid) v = lrelu(ui[k] + uj[k] + b0[k]);
            Z0[k*64+e] = v;
        }
    }
    __syncthreads();
    gemm64<true,true>(Z0, Za, Wsp, b1, eg, og);
    __syncthreads();
    layer10(Za, wsh, part, e, kh);
    __syncthreads();

    float* Xg = Xout + (size_t)g*X_PER_G;
#pragma unroll
    for (int p = 0; p < 4; p++){
        int idx = tid + p*128;              // 0..511
        int ee = idx >> 3, side = (idx >> 2) & 1, a = idx & 3;
        if (ee < ecnt){
            int i = si[ee], j = sj[ee];
            const float* p0 = part + ee*10;
            const float* p1 = part + 640 + ee*10;
            int s0=c_smat[a*4], s1=c_smat[a*4+1], s2=c_smat[a*4+2], s3=c_smat[a*4+3];
            float4 v = make_float4(p0[s0]+p1[s0]+b2[s0], p0[s1]+p1[s1]+b2[s1],
                                   p0[s2]+p1[s2]+b2[s2], p0[s3]+p1[s3]+b2[s3]);
            int bi = side ? j : i;
            int bj = side ? i : j;
            *reinterpret_cast<float4*>(Xg + (bi*4+a)*160 + bj*4) = v;
        }
    }
}

// ---------------------------------------------------------------------------
extern "C" void kernel_launch(void* const* d_in, const int* in_sizes, int n_in,
                              void* d_out, int out_size)
{
    const float* x  = (const float*)d_in[0];
    // d_in[1] edge_index (unused: complete graph), d_in[3] edge_map (unused)
    const int*   ud = (const int*)d_in[2];   // int32 (JAX default x64 disabled)
    const float* Wg0 = (const float*)d_in[4];  const float* bg0 = (const float*)d_in[5];
    const float* Wg1 = (const float*)d_in[6];  const float* bg1 = (const float*)d_in[7];
    const float* Wg2 = (const float*)d_in[8];  const float* bg2 = (const float*)d_in[9];
    const float* Wn0 = (const float*)d_in[10]; const float* bn0 = (const float*)d_in[11];
    const float* Wn1 = (const float*)d_in[12]; const float* bn1 = (const float*)d_in[13];
    const float* Wn2 = (const float*)d_in[14]; const float* bn2 = (const float*)d_in[15];
    const float* We0 = (const float*)d_in[16]; const float* be0 = (const float*)d_in[17];
    const float* We1 = (const float*)d_in[18]; const float* be1 = (const float*)d_in[19];
    const float* We2 = (const float*)d_in[20]; const float* be2 = (const float*)d_in[21];

    // Adaptive output layout: reference returns (h, X). Depending on how the
    // harness flattens the tuple, d_out may hold both (h first), only X, or
    // only h. Anything not in d_out goes to __device__ scratch.
    float* hout;
    float* Xout;
    size_t osz = (size_t)out_size;
    if (osz >= (size_t)H_ELEMS + X_ELEMS){
        hout = (float*)d_out;
        Xout = (float*)d_out + H_ELEMS;
    } else if (osz >= X_ELEMS){
        cudaGetSymbolAddress((void**)&hout, g_h);
        Xout = (float*)d_out;
    } else {
        hout = (float*)d_out;
        cudaGetSymbolAddress((void**)&Xout, g_x);
    }

    cudaFuncSetAttribute(node_kernel, cudaFuncAttributeMaxDynamicSharedMemorySize,
                         K2_SMEM_FLOATS*4);
    cudaFuncSetAttribute(edge_kernel, cudaFuncAttributeMaxDynamicSharedMemorySize,
                         K3_SMEM_FLOATS*4);

    gcn_kernel<<<NG, 128>>>(x, Wg0, bg0, Wg1, bg1, Wg2, bg2, hout);
    node_kernel<<<NODES/64, 128, K2_SMEM_FLOATS*4>>>(hout, Wn0, bn0, Wn1, bn1,
                                                     Wn2, bn2, We0, Xout);
    edge_kernel<<<dim3(13, NG), 128, K3_SMEM_FLOATS*4>>>(ud, be0, We1, be1,
                                                         We2, be2, Xout);
}